// round 17
// baseline (speedup 1.0000x reference)
#include <cuda_runtime.h>

// QLSTM closed form:
//   qgate(x, p)[:, w] = prod_{j<=w} cos(p[j,1]) * cos(y[:,j] + p[j,0])
// LSTM cell + residual + layernorm; sequential over T only, independent per row.

#define TT 128
#define BB 256
#define DD 64
#define HH 10
#define G4 40   // 4 gates * H
#define WROW (DD + HH)   // 74: row stride of Wg

// Layout: pre[b][t][c], c = g*10 + w  (row-contiguous; warp streams 20KB)
__device__ float g_pre[BB * TT * G4];

__device__ __forceinline__ float tanh_fast(float x) {
    float y;
    asm("tanh.approx.f32 %0, %1;" : "=f"(y) : "f"(x));
    return y;
}

// Compiler-only ordering fence: prevents ptxas from hoisting the exchange LDS
// above the STS. HW ordering within one converged warp is provided by the
// in-order per-warp MIO pipeline (no WARPSYNC needed on the chain).
#define COMPILER_FENCE() asm volatile("" ::: "memory")

// ---------------------------------------------------------------------------
// Kernel 1 (proven, unchanged): pre[b][t][:] = fold_bias + x@Wg^T
// fold_bias = b_g[w] + p_g[w,0] + sum_j lnb_j * Whh_g[w,j]
// ---------------------------------------------------------------------------
__global__ void __launch_bounds__(128) k_pre(
    const float* __restrict__ x,
    const float* __restrict__ Wf, const float* __restrict__ bf, const float* __restrict__ pf,
    const float* __restrict__ Wi, const float* __restrict__ bi, const float* __restrict__ pi,
    const float* __restrict__ Wu, const float* __restrict__ bu, const float* __restrict__ pu,
    const float* __restrict__ Wo, const float* __restrict__ bo, const float* __restrict__ po,
    const float* __restrict__ lnb_)
{
    int tid  = threadIdx.x;
    int warp = tid >> 5, l = tid & 31;
    int wg   = blockIdx.x * 4 + warp;     // 0..4095
    int b    = wg & (BB - 1);
    int tg   = wg >> 8;                    // 0..15
    int tbase = tg * 8;

    int g0 = l / 10, w0 = l - g0 * 10;
    const float* Wg0 = (g0 == 0) ? Wf : (g0 == 1) ? Wi : (g0 == 2) ? Wu : Wo;
    const float* bg0 = (g0 == 0) ? bf : (g0 == 1) ? bi : (g0 == 2) ? bu : bo;
    const float* pg0 = (g0 == 0) ? pf : (g0 == 1) ? pi : (g0 == 2) ? pu : po;

    float wa[DD];
    #pragma unroll
    for (int d = 0; d < DD; d++) wa[d] = Wg0[w0 * WROW + d];
    float bias0 = bg0[w0] + pg0[w0 * 3 + 0];
    #pragma unroll
    for (int j = 0; j < HH; j++)
        bias0 = fmaf(lnb_[j], Wg0[w0 * WROW + DD + j], bias0);

    float wb[DD];
    float bias1 = 0.f;
    int w1 = 2 + l;
    #pragma unroll
    for (int d = 0; d < DD; d++) wb[d] = (l < 8) ? Wo[w1 * WROW + d] : 0.f;
    if (l < 8) {
        bias1 = bo[w1] + po[w1 * 3 + 0];
        #pragma unroll
        for (int j = 0; j < HH; j++)
            bias1 = fmaf(lnb_[j], Wo[w1 * WROW + DD + j], bias1);
    }

    for (int i = 0; i < 8; i++) {
        int t = tbase + i;
        const float* xr = x + ((size_t)t * BB + b) * DD;
        float x0 = xr[l];
        float x1 = xr[l + 32];

        float a0 = bias0, a0b = 0.f;
        float a1 = bias1, a1b = 0.f;
        #pragma unroll
        for (int d = 0; d < 32; d += 2) {
            float xd0 = __shfl_sync(0xffffffffu, x0, d);
            float xd1 = __shfl_sync(0xffffffffu, x0, d + 1);
            a0  = fmaf(xd0, wa[d], a0);
            a0b = fmaf(xd1, wa[d + 1], a0b);
            a1  = fmaf(xd0, wb[d], a1);
            a1b = fmaf(xd1, wb[d + 1], a1b);
        }
        #pragma unroll
        for (int d = 0; d < 32; d += 2) {
            float xd0 = __shfl_sync(0xffffffffu, x1, d);
            float xd1 = __shfl_sync(0xffffffffu, x1, d + 1);
            a0  = fmaf(xd0, wa[32 + d], a0);
            a0b = fmaf(xd1, wa[32 + d + 1], a0b);
            a1  = fmaf(xd0, wb[32 + d], a1);
            a1b = fmaf(xd1, wb[32 + d + 1], a1b);
        }
        float* pr = g_pre + ((size_t)b * TT + t) * G4;
        pr[l] = a0 + a0b;
        if (l < 8) pr[32 + l] = a1 + a1b;
    }
}

// ---------------------------------------------------------------------------
// Kernel 2: R11 champion body verbatim, with __syncwarp() replaced by a
// compiler-only fence (single converged warp; MIO per-warp in-order gives
// the HW STS->LDS ordering; WARPSYNC was ~23 cyc on the critical chain).
// qs layout per warp/parity (48 floats): gate g segment at [g*12..g*12+9].
// ch0 lanes write g0*12+w0 (lanes 30,31 = gate o wires 0,1 -> 36,37);
// ch1 lanes (l<8) write 36+(2+l) -> gate o wires 2..9 at 38..45.
// ---------------------------------------------------------------------------
__global__ void __launch_bounds__(64) k_scan(
    const float* __restrict__ Wf, const float* __restrict__ pf,
    const float* __restrict__ Wi, const float* __restrict__ pi,
    const float* __restrict__ Wu, const float* __restrict__ pu,
    const float* __restrict__ Wo, const float* __restrict__ po,
    const float* __restrict__ lng_, const float* __restrict__ lnb_,
    float* __restrict__ out)
{
    __shared__ __align__(16) float qs[2][2][48];

    int tid  = threadIdx.x;
    int warp = tid >> 5, l = tid & 31;
    int row  = blockIdx.x * 2 + warp;

    // ch0: lane l -> channel l: gate g0 = l/10 (0..3), wire w0 = l%10
    // (lanes 30,31 = gate o wires 0,1)
    int g0 = l / 10, w0 = l - g0 * 10;
    const float* Wg0 = (g0 == 0) ? Wf : (g0 == 1) ? Wi : (g0 == 2) ? Wu : Wo;
    const float* Pg0 = (g0 == 0) ? pf : (g0 == 1) ? pi : (g0 == 2) ? pu : po;

    float cth1_0 = cosf(Pg0[w0 * 3 + 1]);
    // sigmoid half-fold on wire-0 channels of sigmoid gates: f(l=0), i(l=10), o(l=30)
    if (l == 0 || l == 10 || l == 30) cth1_0 *= 0.5f;
    float whh0[HH], sw0 = 0.f;
    #pragma unroll
    for (int j = 0; j < HH; j++) {
        whh0[j] = Wg0[w0 * WROW + DD + j] * lng_[j];
        sw0 += whh0[j];
    }

    // ch1: lanes 0..7 -> gate o wires 2..9 (channels 32..39)
    int w1 = 2 + l;
    float cth1_1 = 0.f, sw1 = 0.f;
    float whh1[HH];
    #pragma unroll
    for (int j = 0; j < HH; j++) whh1[j] = 0.f;
    if (l < 8) {
        cth1_1 = cosf(po[w1 * 3 + 1]);
        #pragma unroll
        for (int j = 0; j < HH; j++) {
            whh1[j] = Wo[w1 * WROW + DD + j] * lng_[j];
            sw1 += whh1[j];
        }
    }

    float lng_l = 0.f, lnb_l = 0.f;
    if (l < HH) { lng_l = lng_[l]; lnb_l = lnb_[l]; }

    float hr[HH];
    #pragma unroll
    for (int j = 0; j < HH; j++) hr[j] = 0.f;
    float mu = 0.f, rs = 0.f, hown = 0.f, creg = 0.f;

    const float* prow = g_pre + (size_t)row * TT * G4;
    float preA0 = prow[l];
    float preA1 = (l < 8) ? prow[32 + l] : 0.f;
    float preB0 = prow[G4 + l];
    float preB1 = (l < 8) ? prow[G4 + 32 + l] : 0.f;
    float k0 = preA0, k1 = preA1;     // rs = mu = 0 at t=0

    float* outp = out + (size_t)row * HH;
    const size_t ostride = (size_t)BB * HH;

#define STEP_BODY(PF0, PF1)                                                     \
    {                                                                           \
        float a0 = 0.f, a1 = 0.f, a2 = 0.f, a3 = 0.f;                           \
        float c0 = 0.f, c1 = 0.f, c2 = 0.f, c3 = 0.f;                           \
        a0 = fmaf(hr[0], whh0[0], a0);  c0 = fmaf(hr[0], whh1[0], c0);          \
        a1 = fmaf(hr[1], whh0[1], a1);  c1 = fmaf(hr[1], whh1[1], c1);          \
        a2 = fmaf(hr[2], whh0[2], a2);  c2 = fmaf(hr[2], whh1[2], c2);          \
        a3 = fmaf(hr[3], whh0[3], a3);  c3 = fmaf(hr[3], whh1[3], c3);          \
        a0 = fmaf(hr[4], whh0[4], a0);  c0 = fmaf(hr[4], whh1[4], c0);          \
        a1 = fmaf(hr[5], whh0[5], a1);  c1 = fmaf(hr[5], whh1[5], c1);          \
        a2 = fmaf(hr[6], whh0[6], a2);  c2 = fmaf(hr[6], whh1[6], c2);          \
        a3 = fmaf(hr[7], whh0[7], a3);  c3 = fmaf(hr[7], whh1[7], c3);          \
        a0 = fmaf(hr[8], whh0[8], a0);  c0 = fmaf(hr[8], whh1[8], c0);          \
        a1 = fmaf(hr[9], whh0[9], a1);  c1 = fmaf(hr[9], whh1[9], c1);          \
        float dot0 = (a0 + a1) + (a2 + a3);                                     \
        float dot1 = (c0 + c1) + (c2 + c3);                                     \
        float y0 = fmaf(rs, dot0, k0);                                          \
        float y1 = fmaf(rs, dot1, k1);                                          \
        float q0 = cth1_0 * __cosf(y0);                                         \
        float q1 = cth1_1 * __cosf(y1);                                         \
        int par = t & 1;                                                        \
        qs[warp][par][g0 * 12 + w0] = q0;                                       \
        if (l < 8) qs[warp][par][36 + w1] = q1;                                 \
        COMPILER_FENCE();                                                       \
        /* own-gate masked prefix tree (gate g0 segment at g0*12) */            \
        const float* sp = &qs[warp][par][g0 * 12];                              \
        float4 va = *(const float4*)sp;                                         \
        float4 vb = *(const float4*)(sp + 4);                                   \
        float2 vc = *(const float2*)(sp + 8);                                   \
        float m1 = va.x * ((w0 >= 1) ? va.y : 1.f);                             \
        float m2 = ((w0 >= 2) ? va.z : 1.f) * ((w0 >= 3) ? va.w : 1.f);         \
        float m3 = ((w0 >= 4) ? vb.x : 1.f) * ((w0 >= 5) ? vb.y : 1.f);         \
        float m4 = ((w0 >= 6) ? vb.z : 1.f) * ((w0 >= 7) ? vb.w : 1.f);         \
        float m5 = ((w0 >= 8) ? vc.x : 1.f) * ((w0 >= 9) ? vc.y : 1.f);         \
        float p1v = ((m1 * m2) * (m3 * m4)) * m5;                               \
        /* gate-o masked prefix tree (segment at 36; valid for lanes 0..9) */   \
        const float* sq = &qs[warp][par][36];                                   \
        float4 ua = *(const float4*)sq;                                         \
        float4 ub = *(const float4*)(sq + 4);                                   \
        float2 uc = *(const float2*)(sq + 8);                                   \
        float n1 = ua.x * ((w0 >= 1) ? ua.y : 1.f);                             \
        float n2 = ((w0 >= 2) ? ua.z : 1.f) * ((w0 >= 3) ? ua.w : 1.f);         \
        float n3 = ((w0 >= 4) ? ub.x : 1.f) * ((w0 >= 5) ? ub.y : 1.f);         \
        float n4 = ((w0 >= 6) ? ub.z : 1.f) * ((w0 >= 7) ? ub.w : 1.f);         \
        float n5 = ((w0 >= 8) ? uc.x : 1.f) * ((w0 >= 9) ? uc.y : 1.f);         \
        float p2v = ((n1 * n2) * (n3 * n4)) * n5;                               \
        float pI = __shfl_sync(0xffffffffu, p1v, l + 10);                       \
        float pU = __shfl_sync(0xffffffffu, p1v, l + 20);                       \
        float fg = fmaf(0.5f, tanh_fast(p1v), 0.5f);                            \
        float ig = fmaf(0.5f, tanh_fast(pI),  0.5f);                            \
        float gg = tanh_fast(pU);                                               \
        float og = fmaf(0.5f, tanh_fast(p2v), 0.5f);                            \
        creg = fmaf(fg, creg, ig * gg);                                         \
        float hval = fmaf(og, tanh_fast(creg), hown);                           \
        _Pragma("unroll")                                                       \
        for (int j = 0; j < HH; j++) hr[j] = __shfl_sync(0xffffffffu, hval, j); \
        float sA = 0.f, sB = 0.f, qA = 0.f, qB = 0.f;                           \
        _Pragma("unroll")                                                       \
        for (int j = 0; j < HH; j += 2) {                                       \
            sA += hr[j];                                                        \
            sB += hr[j + 1];                                                    \
            qA = fmaf(hr[j],     hr[j],     qA);                                \
            qB = fmaf(hr[j + 1], hr[j + 1], qB);                                \
        }                                                                       \
        mu = (sA + sB) * 0.1f;                                                  \
        rs = rsqrtf(fmaf(-mu, mu, (qA + qB) * 0.1f) + 1e-5f);                   \
        hown = fmaf((hval - mu) * rs, lng_l, lnb_l);                            \
        if (l < HH) outp[l] = hown;                                             \
        outp += ostride;                                                        \
        preA0 = preB0; preA1 = preB1;                                           \
        preB0 = (PF0); preB1 = (PF1);                                           \
        float rsmu = rs * mu;                                                   \
        k0 = fmaf(-rsmu, sw0, preA0);                                           \
        k1 = fmaf(-rsmu, sw1, preA1);                                           \
    }

    #pragma unroll 2
    for (int t = 0; t < TT - 2; t++) {
        const float* pn = prow + (size_t)(t + 2) * G4;
        float preC0 = pn[l];
        float preC1 = (l < 8) ? pn[32 + l] : 0.f;
        STEP_BODY(preC0, preC1)
    }
    for (int t = TT - 2; t < TT; t++) {
        STEP_BODY(0.f, 0.f)
    }
#undef STEP_BODY

    if (l < HH) {
        out[(size_t)TT * BB * HH + (size_t)row * HH + l]           = hown;
        out[(size_t)TT * BB * HH + (size_t)BB * HH + row * HH + l] = creg;
    }
}

extern "C" void kernel_launch(void* const* d_in, const int* in_sizes, int n_in,
                              void* d_out, int out_size)
{
    const float* x   = (const float*)d_in[0];
    const float* Wf  = (const float*)d_in[1];
    const float* bf  = (const float*)d_in[2];
    const float* pf  = (const float*)d_in[3];
    const float* Wi  = (const float*)d_in[4];
    const float* bi  = (const float*)d_in[5];
    const float* pi_ = (const float*)d_in[6];
    const float* Wu  = (const float*)d_in[7];
    const float* bu  = (const float*)d_in[8];
    const float* pu  = (const float*)d_in[9];
    const float* Wo  = (const float*)d_in[10];
    const float* bo  = (const float*)d_in[11];
    const float* po  = (const float*)d_in[12];
    const float* lng = (const float*)d_in[13];
    const float* lnb = (const float*)d_in[14];

    k_pre<<<1024, 128>>>(x, Wf, bf, pf, Wi, bi, pi_, Wu, bu, pu, Wo, bo, po, lnb);
    k_scan<<<BB / 2, 64>>>(Wf, pf, Wi, pi_, Wu, pu, Wo, po, lng, lnb, (float*)d_out);
}